// round 14
// baseline (speedup 1.0000x reference)
#include <cuda_runtime.h>
#include <cstdint>

#define NUM_SUB 16
#define CBSZ    1024
#define SUBD    64
#define NTOK    16384
#define EMBD    1024
#define TPB     128
#define QELEMS  ((size_t)NTOK * EMBD)

// smem byte offsets
#define SXT_B   0        // ull[32][128] x pairs, interleaved layout   (32768 B)
#define SCC_B   32768    // chunk double buffer: 2 x 8192 B            (16384 B)
#define SC2_B   49152    // float[1024]                                (4096 B)
#define SX2_B   53248    // float[128]                                 (512 B)
#define SMEM_BYTES 53760
// candidate buffers alias chunk region after last chunk:
#define CD_B    32768    // float[128][8]
#define CI_B    36864    // int[128][8]

__device__ float g_c2[NUM_SUB * CBSZ];

// ---------- packed f32x2 / async helpers ----------
__device__ __forceinline__ unsigned long long pk2(float lo, float hi) {
    unsigned long long r;
    asm("mov.b64 %0, {%1, %2};" : "=l"(r) : "f"(lo), "f"(hi));
    return r;
}
__device__ __forceinline__ unsigned long long ffma2(unsigned long long a,
                                                    unsigned long long b,
                                                    unsigned long long c) {
    unsigned long long d;
    asm("fma.rn.f32x2 %0, %1, %2, %3;" : "=l"(d) : "l"(a), "l"(b), "l"(c));
    return d;
}
__device__ __forceinline__ void unpk2(unsigned long long a, float& lo, float& hi) {
    unsigned int l, h;
    asm("mov.b64 {%0, %1}, %2;" : "=r"(l), "=r"(h) : "l"(a));
    lo = __uint_as_float(l); hi = __uint_as_float(h);
}
__device__ __forceinline__ unsigned int smem_u32(const void* p) {
    unsigned int a;
    asm("{ .reg .u64 t; cvta.to.shared.u64 t, %1; cvt.u32.u64 %0, t; }" : "=r"(a) : "l"(p));
    return a;
}
__device__ __forceinline__ void cp_async16(unsigned int dst, const void* src) {
    asm volatile("cp.async.cg.shared.global [%0], [%1], 16;" :: "r"(dst), "l"(src));
}

// Exact XLA:GPU warp-row-reduce sum of squares (R8-proven; do not alter):
// leaf_t = rn(rn(v[t]^2) + rn(v[t+32]^2)); butterfly 16,8,4,2,1.
__device__ __forceinline__ float sumsq_xla64(const float* __restrict__ v) {
    float p[32];
#pragma unroll
    for (int t = 0; t < 32; t++)
        p[t] = __fadd_rn(__fmul_rn(v[t], v[t]),
                         __fmul_rn(v[t + 32], v[t + 32]));
#pragma unroll
    for (int off = 16; off >= 1; off >>= 1)
#pragma unroll 32
        for (int t = 0; t < off; t++)
            p[t] = __fadd_rn(p[t], p[t + off]);
    return p[0];
}

// ---- kernel A: precompute c2 once (exact XLA scheme) ----
__global__ void c2_kernel(const float* __restrict__ cb) {
    const int m = blockIdx.x;
    const int k = threadIdx.x;
    float cv[SUBD];
    const float4* cr = (const float4*)(cb + ((size_t)m * CBSZ + k) * SUBD);
#pragma unroll
    for (int i = 0; i < 16; i++) {
        float4 v = cr[i];
        cv[4*i] = v.x; cv[4*i+1] = v.y; cv[4*i+2] = v.z; cv[4*i+3] = v.w;
    }
    g_c2[m * CBSZ + k] = sumsq_xla64(cv);
}

// ---- kernel B: main. out: [quantized 16777216 f32][indices 262144 f32] ----
__global__ __launch_bounds__(TPB, 4)
void pq_main(const float* __restrict__ emb,
             const float* __restrict__ cb,
             float*       __restrict__ out)
{
    extern __shared__ char sm[];
    unsigned long long* sxt = (unsigned long long*)(sm + SXT_B);
    float*              sc2 = (float*)(sm + SC2_B);
    float*              sx2 = (float*)(sm + SX2_B);
    float*              cd  = (float*)(sm + CD_B);
    int*                ci  = (int*)(sm + CI_B);

    const int m       = blockIdx.y;
    const int tid     = threadIdx.x;
    const int lane    = tid & 31;
    const int w       = tid >> 5;
    const int tokBase = blockIdx.x * TPB;
    const float* cbm  = cb + (size_t)m * CBSZ * SUBD;

    // interleaved position: tokens (lane, lane+32) adjacent; (lane+64, lane+96) adjacent
    const int g   = tid >> 6;
    const int t6  = tid & 63;
    const int pos = g * 64 + 2 * (t6 & 31) + (t6 >> 5);

    // ---- stage my token: x2 (exact XLA) + packed pairs into sxt ----
    {
        float xs[SUBD];
        const float4* p = (const float4*)(emb + (size_t)(tokBase + tid) * EMBD + m * SUBD);
#pragma unroll
        for (int i = 0; i < 16; i++) {
            float4 v = p[i];
            xs[4*i] = v.x; xs[4*i+1] = v.y; xs[4*i+2] = v.z; xs[4*i+3] = v.w;
        }
        sx2[tid] = sumsq_xla64(xs);
#pragma unroll
        for (int kp = 0; kp < 32; kp++)
            sxt[kp * 128 + pos] = pk2(xs[2*kp], xs[2*kp+1]);
    }
#pragma unroll
    for (int i = 0; i < 8; i++)
        sc2[tid + i * TPB] = g_c2[m * CBSZ + tid + i * TPB];

    // ---- prologue: stage chunk 0 into buffer 0 ----
    {
        unsigned int dst = smem_u32(sm + SCC_B) + tid * 16;
#pragma unroll
        for (int it = 0; it < 4; it++) {
            int idx = tid + it * TPB;            // float4 index 0..511
            int cw  = idx >> 4, i4 = idx & 15;
            cp_async16(dst + it * TPB * 16, cbm + (size_t)cw * SUBD + i4 * 4);
        }
        asm volatile("cp.async.commit_group;");
    }

    __syncthreads();   // sx2/sxt/sc2 staging visible before cross-thread reads (R13 bug fix)

    float x2r[4];
#pragma unroll
    for (int t = 0; t < 4; t++) x2r[t] = sx2[lane + 32 * t];

    float bd0[4], bd1[4];
    int   bi0[4], bi1[4];
#pragma unroll
    for (int t = 0; t < 4; t++) { bd0[t]=3.4e38f; bd1[t]=3.4e38f; bi0[t]=0; bi1[t]=0; }

    for (int ch = 0; ch < 32; ch++) {
        // prefetch next chunk into other buffer
        if (ch + 1 < 32) {
            int c1 = (ch + 1) * 32;
            unsigned int dst = smem_u32(sm + SCC_B + ((ch + 1) & 1) * 8192) + tid * 16;
#pragma unroll
            for (int it = 0; it < 4; it++) {
                int idx = tid + it * TPB;
                int cw  = idx >> 4, i4 = idx & 15;
                cp_async16(dst + it * TPB * 16, cbm + (size_t)(c1 + cw) * SUBD + i4 * 4);
            }
            asm volatile("cp.async.commit_group;");
            asm volatile("cp.async.wait_group 1;");
        } else {
            asm volatile("cp.async.wait_group 0;");
        }
        __syncthreads();   // chunk ch visible to all warps

        const unsigned long long* ccw =
            (const unsigned long long*)(sm + SCC_B + (ch & 1) * 8192) + (w * 8) * 32;
        const int c0 = ch * 32;

        unsigned long long acc[4][8];
#pragma unroll
        for (int t = 0; t < 4; t++)
#pragma unroll
            for (int c = 0; c < 8; c++) acc[t][c] = 0ull;

#pragma unroll 4
        for (int kp = 0; kp < 32; kp += 2) {
            ulonglong2 xab0 = *(const ulonglong2*)&sxt[kp * 128 + 2 * lane];
            ulonglong2 xcd0 = *(const ulonglong2*)&sxt[kp * 128 + 64 + 2 * lane];
            ulonglong2 xab1 = *(const ulonglong2*)&sxt[(kp + 1) * 128 + 2 * lane];
            ulonglong2 xcd1 = *(const ulonglong2*)&sxt[(kp + 1) * 128 + 64 + 2 * lane];
#pragma unroll
            for (int c = 0; c < 8; c++) {
                ulonglong2 cc = *(const ulonglong2*)&ccw[c * 32 + kp];  // broadcast
                acc[0][c] = ffma2(xab0.x, cc.x, acc[0][c]);
                acc[1][c] = ffma2(xab0.y, cc.x, acc[1][c]);
                acc[2][c] = ffma2(xcd0.x, cc.x, acc[2][c]);
                acc[3][c] = ffma2(xcd0.y, cc.x, acc[3][c]);
                acc[0][c] = ffma2(xab1.x, cc.y, acc[0][c]);
                acc[1][c] = ffma2(xab1.y, cc.y, acc[1][c]);
                acc[2][c] = ffma2(xcd1.x, cc.y, acc[2][c]);
                acc[3][c] = ffma2(xcd1.y, cc.y, acc[3][c]);
            }
        }

        // epilogue: dist + top-2 screen
#pragma unroll
        for (int c = 0; c < 8; c++) {
            int   cw  = c0 + w * 8 + c;
            float c2v = sc2[cw];
#pragma unroll
            for (int t = 0; t < 4; t++) {
                float lo, hi;
                unpk2(acc[t][c], lo, hi);
                float dot  = __fadd_rn(lo, hi);
                float dist = __fadd_rn(__fsub_rn(x2r[t], __fmul_rn(2.0f, dot)), c2v);
                if (dist < bd1[t]) {
                    if (dist < bd0[t]) { bd1[t]=bd0[t]; bi1[t]=bi0[t]; bd0[t]=dist; bi0[t]=cw; }
                    else               { bd1[t]=dist; bi1[t]=cw; }
                }
            }
        }
        __syncthreads();   // done reading chunk ch before its buffer is re-staged
    }

    // ---- merge candidates across 4 warps (alias chunk region) ----
#pragma unroll
    for (int t = 0; t < 4; t++) {
        int tok = lane + 32 * t;
        cd[tok * 8 + 2 * w]     = bd0[t];
        cd[tok * 8 + 2 * w + 1] = bd1[t];
        ci[tok * 8 + 2 * w]     = bi0[t];
        ci[tok * 8 + 2 * w + 1] = bi1[t];
    }
    __syncthreads();

    // ---- per-token winner: merge 8 + margin-gated exact rescore (R8 scheme) ----
    {
        const int tok = tid;
        float d0 = 3.4e38f, d1 = 3.4e38f;
        int   k0 = 0x7fffffff;
#pragma unroll
        for (int i = 0; i < 8; i++) {
            float d = cd[tok * 8 + i];
            int  kk = ci[tok * 8 + i];
            if (d < d0 || (d == d0 && kk < k0)) { d1 = d0; d0 = d; k0 = kk; }
            else if (d < d1) d1 = d;
        }
        int win = k0;
        if (__fsub_rn(d1, d0) < 1e-3f) {
            float xloc[SUBD];
#pragma unroll
            for (int kp = 0; kp < 32; kp++)
                unpk2(sxt[kp * 128 + pos], xloc[2*kp], xloc[2*kp+1]);
            float x2e = sx2[tok];
            float bde = 3.4e38f; int bke = 0x7fffffff;
            float cut = __fadd_rn(d0, 1e-3f);
#pragma unroll 1
            for (int i = 0; i < 8; i++) {
                if (cd[tok * 8 + i] <= cut) {
                    int kk = ci[tok * 8 + i];
                    const float4* cr = (const float4*)(cbm + (size_t)kk * SUBD);
                    float dot = 0.f;
#pragma unroll
                    for (int i2 = 0; i2 < 16; i2++) {
                        float4 c = cr[i2];
                        dot = __fmaf_rn(xloc[4*i2],     c.x, dot);
                        dot = __fmaf_rn(xloc[4*i2 + 1], c.y, dot);
                        dot = __fmaf_rn(xloc[4*i2 + 2], c.z, dot);
                        dot = __fmaf_rn(xloc[4*i2 + 3], c.w, dot);
                    }
                    float dist = __fadd_rn(__fsub_rn(x2e, __fmul_rn(2.0f, dot)), sc2[kk]);
                    if (dist < bde || (dist == bde && kk < bke)) { bde = dist; bke = kk; }
                }
            }
            win = bke;
        }
        const float4* wv = (const float4*)(cbm + (size_t)win * SUBD);
        float4* qo = (float4*)(out + (size_t)(tokBase + tok) * EMBD + m * SUBD);
#pragma unroll
        for (int i = 0; i < 16; i++) qo[i] = wv[i];
        out[QELEMS + (size_t)(tokBase + tok) * NUM_SUB + m] = (float)win;
    }
}

extern "C" void kernel_launch(void* const* d_in, const int* in_sizes, int n_in,
                              void* d_out, int out_size)
{
    const float* emb = (const float*)d_in[0];  // [8,2048,1024] f32
    const float* cb  = (const float*)d_in[1];  // [16,1024,64]  f32

    c2_kernel<<<NUM_SUB, 1024>>>(cb);

    cudaFuncSetAttribute(pq_main,
                         cudaFuncAttributeMaxDynamicSharedMemorySize, SMEM_BYTES);
    dim3 grid(NTOK / TPB, NUM_SUB);            // (128, 16)
    pq_main<<<grid, TPB, SMEM_BYTES>>>(emb, cb, (float*)d_out);
}

// round 15
// speedup vs baseline: 2.1126x; 2.1126x over previous
#include <cuda_runtime.h>
#include <cstdint>

#define NUM_SUB 16
#define CBSZ    1024
#define SUBD    64
#define NTOK    16384
#define EMBD    1024
#define TPB     128
#define QELEMS  ((size_t)NTOK * EMBD)
#define ROWP    68          // padded row (floats) for conflict-free LDS
#define BAND    0.5f        // exact-rescore margin (>> tf32 screen error)

// smem byte offsets
#define SXF_B   0                       // float[128][68] x, padded     (34816 B)
#define SCC_B   34816                   // chunk dbuf: 2 x 32*68*4      (17408 B)
#define SC2_B   52224                   // float[1024]                  (4096 B)
#define SX2_B   56320                   // float[128]                   (512 B)
#define SMEM_BYTES 56832
// candidate buffers alias chunk region after last chunk:
#define CD_B    SCC_B                   // float[128][12]
#define CI_B    (SCC_B + 6144)          // int[128][12]

__device__ float g_c2[NUM_SUB * CBSZ];

__device__ __forceinline__ unsigned int smem_u32(const void* p) {
    unsigned int a;
    asm("{ .reg .u64 t; cvta.to.shared.u64 t, %1; cvt.u32.u64 %0, t; }" : "=r"(a) : "l"(p));
    return a;
}
__device__ __forceinline__ void cp_async16(unsigned int dst, const void* src) {
    asm volatile("cp.async.cg.shared.global [%0], [%1], 16;" :: "r"(dst), "l"(src));
}
// m16n8k8 tf32 mma; raw fp32 bits as tf32 operands (HW truncates mantissa)
__device__ __forceinline__ void mma_tf32(float& d0, float& d1, float& d2, float& d3,
                                         unsigned a0, unsigned a1, unsigned a2, unsigned a3,
                                         unsigned b0, unsigned b1) {
    asm("mma.sync.aligned.m16n8k8.row.col.f32.tf32.tf32.f32 "
        "{%0,%1,%2,%3}, {%4,%5,%6,%7}, {%8,%9}, {%0,%1,%2,%3};"
        : "+f"(d0), "+f"(d1), "+f"(d2), "+f"(d3)
        : "r"(a0), "r"(a1), "r"(a2), "r"(a3), "r"(b0), "r"(b1));
}

// Exact XLA:GPU warp-row-reduce sum of squares (R8-proven; do not alter):
__device__ __forceinline__ float sumsq_xla64(const float* __restrict__ v) {
    float p[32];
#pragma unroll
    for (int t = 0; t < 32; t++)
        p[t] = __fadd_rn(__fmul_rn(v[t], v[t]),
                         __fmul_rn(v[t + 32], v[t + 32]));
#pragma unroll
    for (int off = 16; off >= 1; off >>= 1)
#pragma unroll 32
        for (int t = 0; t < off; t++)
            p[t] = __fadd_rn(p[t], p[t + off]);
    return p[0];
}

__global__ void c2_kernel(const float* __restrict__ cb) {
    const int m = blockIdx.x;
    const int k = threadIdx.x;
    float cv[SUBD];
    const float4* cr = (const float4*)(cb + ((size_t)m * CBSZ + k) * SUBD);
#pragma unroll
    for (int i = 0; i < 16; i++) {
        float4 v = cr[i];
        cv[4*i] = v.x; cv[4*i+1] = v.y; cv[4*i+2] = v.z; cv[4*i+3] = v.w;
    }
    g_c2[m * CBSZ + k] = sumsq_xla64(cv);
}

// out: [quantized 16777216 f32][indices 262144 f32]
__global__ __launch_bounds__(TPB, 3)
void pq_main(const float* __restrict__ emb,
             const float* __restrict__ cb,
             float*       __restrict__ out)
{
    extern __shared__ char sm[];
    float* sxf = (float*)(sm + SXF_B);
    float* sc2 = (float*)(sm + SC2_B);
    float* sx2 = (float*)(sm + SX2_B);
    float* cd  = (float*)(sm + CD_B);
    int*   ci  = (int*)(sm + CI_B);

    const int m       = blockIdx.y;
    const int tid     = threadIdx.x;
    const int lane    = tid & 31;
    const int w       = tid >> 5;
    const int gid     = lane >> 2;     // groupID (row within tile)
    const int tig     = lane & 3;      // threadID in group
    const int tokBase = blockIdx.x * TPB;
    const int wbase   = w * 32;        // warp's token offset in block
    const float* cbm  = cb + (size_t)m * CBSZ * SUBD;

    // ---- stage my token into padded smem + exact XLA x2 ----
    {
        float xs[SUBD];
        const float4* p = (const float4*)(emb + (size_t)(tokBase + tid) * EMBD + m * SUBD);
#pragma unroll
        for (int i = 0; i < 16; i++) {
            float4 v = p[i];
            xs[4*i] = v.x; xs[4*i+1] = v.y; xs[4*i+2] = v.z; xs[4*i+3] = v.w;
            *(float4*)&sxf[tid * ROWP + 4 * i] = v;
        }
        sx2[tid] = sumsq_xla64(xs);
    }
#pragma unroll
    for (int i = 0; i < 8; i++)
        sc2[tid + i * TPB] = g_c2[m * CBSZ + tid + i * TPB];

    // ---- prologue: cp.async chunk 0 into buffer 0 (32 cw, padded rows) ----
    {
        unsigned int base = smem_u32(sm + SCC_B);
#pragma unroll
        for (int it = 0; it < 4; it++) {
            int idx = tid + it * TPB;          // 0..511
            int cw  = idx >> 4, i4 = idx & 15;
            cp_async16(base + cw * (ROWP * 4) + i4 * 16,
                       cbm + (size_t)cw * SUBD + i4 * 4);
        }
        asm volatile("cp.async.commit_group;");
    }
    __syncthreads();

    // ---- A fragments for this warp's 32 tokens (register-resident) ----
    unsigned Af[2][8][4];
#pragma unroll
    for (int rt = 0; rt < 2; rt++)
#pragma unroll
        for (int ks = 0; ks < 8; ks++) {
            int r0 = (wbase + rt * 16 + gid) * ROWP + ks * 8 + tig;
            Af[rt][ks][0] = __float_as_uint(sxf[r0]);
            Af[rt][ks][1] = __float_as_uint(sxf[r0 + 8 * ROWP]);
            Af[rt][ks][2] = __float_as_uint(sxf[r0 + 4]);
            Af[rt][ks][3] = __float_as_uint(sxf[r0 + 8 * ROWP + 4]);
        }
    float x2s[4];
#pragma unroll
    for (int s = 0; s < 4; s++)
        x2s[s] = sx2[wbase + (s >> 1) * 16 + gid + 8 * (s & 1)];

    // per-slot top-3 screen candidates
    float td[4][3]; int ti[4][3];
#pragma unroll
    for (int s = 0; s < 4; s++)
#pragma unroll
        for (int j = 0; j < 3; j++) { td[s][j] = 3.4e38f; ti[s][j] = 0; }

    for (int ch = 0; ch < 32; ch++) {
        if (ch + 1 < 32) {
            unsigned int base = smem_u32(sm + SCC_B + ((ch + 1) & 1) * 8704);
            const float* src0 = cbm + (size_t)(ch + 1) * 32 * SUBD;
#pragma unroll
            for (int it = 0; it < 4; it++) {
                int idx = tid + it * TPB;
                int cw  = idx >> 4, i4 = idx & 15;
                cp_async16(base + cw * (ROWP * 4) + i4 * 16,
                           src0 + (size_t)cw * SUBD + i4 * 4);
            }
            asm volatile("cp.async.commit_group;");
            asm volatile("cp.async.wait_group 1;");
        } else {
            asm volatile("cp.async.wait_group 0;");
        }
        __syncthreads();

        const float* cc = (const float*)(sm + SCC_B + (ch & 1) * 8704);
        const int c0 = ch * 32;

#pragma unroll
        for (int nt = 0; nt < 4; nt++) {
            // B fragments: codewords nt*8..nt*8+7, all 8 k-steps
            unsigned bs[8][2];
            const float* bp = cc + (nt * 8 + gid) * ROWP + tig;
#pragma unroll
            for (int ks = 0; ks < 8; ks++) {
                bs[ks][0] = __float_as_uint(bp[ks * 8]);
                bs[ks][1] = __float_as_uint(bp[ks * 8 + 4]);
            }
            float acc[2][4];
#pragma unroll
            for (int rt = 0; rt < 2; rt++) {
                acc[rt][0] = 0.f; acc[rt][1] = 0.f; acc[rt][2] = 0.f; acc[rt][3] = 0.f;
#pragma unroll
                for (int ks = 0; ks < 8; ks++)
                    mma_tf32(acc[rt][0], acc[rt][1], acc[rt][2], acc[rt][3],
                             Af[rt][ks][0], Af[rt][ks][1], Af[rt][ks][2], Af[rt][ks][3],
                             bs[ks][0], bs[ks][1]);
            }
            // epilogue: acc[rt] = {(+0,cwA),(+0,cwA+1),(+8,cwA),(+8,cwA+1)}
            int   cwA = c0 + nt * 8 + 2 * tig;
            float c2a = sc2[cwA], c2b = sc2[cwA + 1];
#pragma unroll
            for (int rt = 0; rt < 2; rt++) {
#pragma unroll
                for (int h = 0; h < 2; h++) {
                    int s = rt * 2 + h;
                    float dA = __fmaf_rn(-2.f, acc[rt][2 * h],     x2s[s]) + c2a;
                    float dB = __fmaf_rn(-2.f, acc[rt][2 * h + 1], x2s[s]) + c2b;
                    if (dA < td[s][2]) {
                        if (dA < td[s][0])      { td[s][2]=td[s][1]; ti[s][2]=ti[s][1]; td[s][1]=td[s][0]; ti[s][1]=ti[s][0]; td[s][0]=dA; ti[s][0]=cwA; }
                        else if (dA < td[s][1]) { td[s][2]=td[s][1]; ti[s][2]=ti[s][1]; td[s][1]=dA; ti[s][1]=cwA; }
                        else                    { td[s][2]=dA; ti[s][2]=cwA; }
                    }
                    if (dB < td[s][2]) {
                        if (dB < td[s][0])      { td[s][2]=td[s][1]; ti[s][2]=ti[s][1]; td[s][1]=td[s][0]; ti[s][1]=ti[s][0]; td[s][0]=dB; ti[s][0]=cwA+1; }
                        else if (dB < td[s][1]) { td[s][2]=td[s][1]; ti[s][2]=ti[s][1]; td[s][1]=dB; ti[s][1]=cwA+1; }
                        else                    { td[s][2]=dB; ti[s][2]=cwA+1; }
                    }
                }
            }
        }
        __syncthreads();   // done reading chunk before restaging its buffer
    }

    // ---- write candidates (12 per token) into aliased buffers ----
#pragma unroll
    for (int s = 0; s < 4; s++) {
        int tok = wbase + (s >> 1) * 16 + gid + 8 * (s & 1);
#pragma unroll
        for (int j = 0; j < 3; j++) {
            cd[tok * 12 + tig * 3 + j] = td[s][j];
            ci[tok * 12 + tig * 3 + j] = ti[s][j];
        }
    }
    __syncthreads();

    // ---- per-token winner: merge 12 + band-gated exact rescore (R8 scheme) ----
    {
        const int tok = tid;
        float d0 = 3.4e38f, d1 = 3.4e38f;
        int   k0 = 0x7fffffff;
#pragma unroll
        for (int i = 0; i < 12; i++) {
            float d = cd[tok * 12 + i];
            int  kk = ci[tok * 12 + i];
            if (d < d0 || (d == d0 && kk < k0)) { d1 = d0; d0 = d; k0 = kk; }
            else if (d < d1) d1 = d;
        }
        int win = k0;
        if (__fsub_rn(d1, d0) < BAND) {
            float xloc[SUBD];
#pragma unroll
            for (int j = 0; j < 16; j++) {
                float4 v = *(const float4*)&sxf[tok * ROWP + 4 * j];
                xloc[4*j] = v.x; xloc[4*j+1] = v.y; xloc[4*j+2] = v.z; xloc[4*j+3] = v.w;
            }
            float x2e = sx2[tok];
            float bde = 3.4e38f; int bke = 0x7fffffff;
            float cut = __fadd_rn(d0, BAND);
#pragma unroll 1
            for (int i = 0; i < 12; i++) {
                if (cd[tok * 12 + i] <= cut) {
                    int kk = ci[tok * 12 + i];
                    const float4* cr = (const float4*)(cbm + (size_t)kk * SUBD);
                    float dot = 0.f;
#pragma unroll
                    for (int i2 = 0; i2 < 16; i2++) {
                        float4 c = cr[i2];
                        dot = __fmaf_rn(xloc[4*i2],     c.x, dot);
                        dot = __fmaf_rn(xloc[4*i2 + 1], c.y, dot);
                        dot = __fmaf_rn(xloc[4*i2 + 2], c.z, dot);
                        dot = __fmaf_rn(xloc[4*i2 + 3], c.w, dot);
                    }
                    float dist = __fadd_rn(__fsub_rn(x2e, __fmul_rn(2.0f, dot)), sc2[kk]);
                    if (dist < bde || (dist == bde && kk < bke)) { bde = dist; bke = kk; }
                }
            }
            win = bke;
        }
        const float4* wv = (const float4*)(cbm + (size_t)win * SUBD);
        float4* qo = (float4*)(out + (size_t)(tokBase + tok) * EMBD + m * SUBD);
#pragma unroll
        for (int i = 0; i < 16; i++) qo[i] = wv[i];
        out[QELEMS + (size_t)(tokBase + tok) * NUM_SUB + m] = (float)win;
    }
}

extern "C" void kernel_launch(void* const* d_in, const int* in_sizes, int n_in,
                              void* d_out, int out_size)
{
    const float* emb = (const float*)d_in[0];  // [8,2048,1024] f32
    const float* cb  = (const float*)d_in[1];  // [16,1024,64]  f32

    c2_kernel<<<NUM_SUB, 1024>>>(cb);

    cudaFuncSetAttribute(pq_main,
                         cudaFuncAttributeMaxDynamicSharedMemorySize, SMEM_BYTES);
    dim3 grid(NTOK / TPB, NUM_SUB);            // (128, 16)
    pq_main<<<grid, TPB, SMEM_BYTES>>>(emb, cb, (float*)d_out);
}

// round 16
// speedup vs baseline: 2.1460x; 1.0158x over previous
#include <cuda_runtime.h>
#include <cstdint>

#define NUM_SUB 16
#define CBSZ    1024
#define SUBD    64
#define NTOK    16384
#define EMBD    1024
#define TPB     128
#define QELEMS  ((size_t)NTOK * EMBD)
#define ROWP    68          // padded row (floats) for conflict-free LDS
#define BAND    0.5f        // exact-rescore margin (>> tf32 screen error)

// smem byte offsets
#define SXF_B   0                       // float[128][68] x, padded     (34816 B)
#define SCC_B   34816                   // chunk 3-stage: 3 x 8704      (26112 B)
#define SC2_B   60928                   // float[1024]                  (4096 B)
#define SX2_B   65024                   // float[128]                   (512 B)
#define SMEM_BYTES 65536
// candidate buffers alias chunk region after last chunk:
#define CD_B    SCC_B                   // float[128][12]
#define CI_B    (SCC_B + 6144)          // int[128][12]

__device__ float g_c2[NUM_SUB * CBSZ];

__device__ __forceinline__ unsigned int smem_u32(const void* p) {
    unsigned int a;
    asm("{ .reg .u64 t; cvta.to.shared.u64 t, %1; cvt.u32.u64 %0, t; }" : "=r"(a) : "l"(p));
    return a;
}
__device__ __forceinline__ void cp_async16(unsigned int dst, const void* src) {
    asm volatile("cp.async.cg.shared.global [%0], [%1], 16;" :: "r"(dst), "l"(src));
}
// m16n8k8 tf32 mma; raw fp32 bits as tf32 operands (HW truncates mantissa)
__device__ __forceinline__ void mma_tf32(float& d0, float& d1, float& d2, float& d3,
                                         unsigned a0, unsigned a1, unsigned a2, unsigned a3,
                                         unsigned b0, unsigned b1) {
    asm("mma.sync.aligned.m16n8k8.row.col.f32.tf32.tf32.f32 "
        "{%0,%1,%2,%3}, {%4,%5,%6,%7}, {%8,%9}, {%0,%1,%2,%3};"
        : "+f"(d0), "+f"(d1), "+f"(d2), "+f"(d3)
        : "r"(a0), "r"(a1), "r"(a2), "r"(a3), "r"(b0), "r"(b1));
}

// Exact XLA:GPU warp-row-reduce sum of squares (R8-proven; do not alter):
__device__ __forceinline__ float sumsq_xla64(const float* __restrict__ v) {
    float p[32];
#pragma unroll
    for (int t = 0; t < 32; t++)
        p[t] = __fadd_rn(__fmul_rn(v[t], v[t]),
                         __fmul_rn(v[t + 32], v[t + 32]));
#pragma unroll
    for (int off = 16; off >= 1; off >>= 1)
#pragma unroll 32
        for (int t = 0; t < off; t++)
            p[t] = __fadd_rn(p[t], p[t + off]);
    return p[0];
}

__global__ void c2_kernel(const float* __restrict__ cb) {
    const int m = blockIdx.x;
    const int k = threadIdx.x;
    float cv[SUBD];
    const float4* cr = (const float4*)(cb + ((size_t)m * CBSZ + k) * SUBD);
#pragma unroll
    for (int i = 0; i < 16; i++) {
        float4 v = cr[i];
        cv[4*i] = v.x; cv[4*i+1] = v.y; cv[4*i+2] = v.z; cv[4*i+3] = v.w;
    }
    g_c2[m * CBSZ + k] = sumsq_xla64(cv);
}

// out: [quantized 16777216 f32][indices 262144 f32]
__global__ __launch_bounds__(TPB, 3)
void pq_main(const float* __restrict__ emb,
             const float* __restrict__ cb,
             float*       __restrict__ out)
{
    extern __shared__ char sm[];
    float* sxf = (float*)(sm + SXF_B);
    float* sc2 = (float*)(sm + SC2_B);
    float* sx2 = (float*)(sm + SX2_B);
    float* cd  = (float*)(sm + CD_B);
    int*   ci  = (int*)(sm + CI_B);

    const int m       = blockIdx.y;
    const int tid     = threadIdx.x;
    const int lane    = tid & 31;
    const int w       = tid >> 5;
    const int gid     = lane >> 2;
    const int tig     = lane & 3;
    const int tokBase = blockIdx.x * TPB;
    const int wbase   = w * 32;
    const float* cbm  = cb + (size_t)m * CBSZ * SUBD;

    // ---- stage my token into padded smem + exact XLA x2 ----
    {
        float xs[SUBD];
        const float4* p = (const float4*)(emb + (size_t)(tokBase + tid) * EMBD + m * SUBD);
#pragma unroll
        for (int i = 0; i < 16; i++) {
            float4 v = p[i];
            xs[4*i] = v.x; xs[4*i+1] = v.y; xs[4*i+2] = v.z; xs[4*i+3] = v.w;
            *(float4*)&sxf[tid * ROWP + 4 * i] = v;
        }
        sx2[tid] = sumsq_xla64(xs);
    }
#pragma unroll
    for (int i = 0; i < 8; i++)
        sc2[tid + i * TPB] = g_c2[m * CBSZ + tid + i * TPB];

    // ---- prologue: stage chunks 0 and 1 (stages 0, 1) ----
#pragma unroll
    for (int pc = 0; pc < 2; pc++) {
        unsigned int base = smem_u32(sm + SCC_B + pc * 8704);
        const float* src0 = cbm + (size_t)pc * 32 * SUBD;
#pragma unroll
        for (int it = 0; it < 4; it++) {
            int idx = tid + it * TPB;
            int cw  = idx >> 4, i4 = idx & 15;
            cp_async16(base + cw * (ROWP * 4) + i4 * 16,
                       src0 + (size_t)cw * SUBD + i4 * 4);
        }
        asm volatile("cp.async.commit_group;");
    }
    __syncthreads();   // sxf/sx2/sc2 staging visible (A-frag loads next)

    // ---- A fragments for this warp's 32 tokens (register-resident) ----
    unsigned Af[2][8][4];
#pragma unroll
    for (int rt = 0; rt < 2; rt++)
#pragma unroll
        for (int ks = 0; ks < 8; ks++) {
            int r0 = (wbase + rt * 16 + gid) * ROWP + ks * 8 + tig;
            Af[rt][ks][0] = __float_as_uint(sxf[r0]);
            Af[rt][ks][1] = __float_as_uint(sxf[r0 + 8 * ROWP]);
            Af[rt][ks][2] = __float_as_uint(sxf[r0 + 4]);
            Af[rt][ks][3] = __float_as_uint(sxf[r0 + 8 * ROWP + 4]);
        }

    // per-slot top-3 screen candidates (screen value: -2*dot + c2; x2 dropped)
    float td[4][3]; int ti[4][3];
#pragma unroll
    for (int s = 0; s < 4; s++)
#pragma unroll
        for (int j = 0; j < 3; j++) { td[s][j] = 3.4e38f; ti[s][j] = 0; }

    for (int ch = 0; ch < 32; ch++) {
        asm volatile("cp.async.wait_group 1;");   // chunk ch arrived (ch+1 may fly)
        __syncthreads();  // all warps see chunk ch AND are done reading ch-1

        // prefetch chunk ch+2 into stage (ch+2)%3 (overwrites ch-1: safe post-barrier)
        if (ch + 2 < 32) {
            unsigned int base = smem_u32(sm + SCC_B + ((ch + 2) % 3) * 8704);
            const float* src0 = cbm + (size_t)(ch + 2) * 32 * SUBD;
#pragma unroll
            for (int it = 0; it < 4; it++) {
                int idx = tid + it * TPB;
                int cw  = idx >> 4, i4 = idx & 15;
                cp_async16(base + cw * (ROWP * 4) + i4 * 16,
                           src0 + (size_t)cw * SUBD + i4 * 4);
            }
        }
        asm volatile("cp.async.commit_group;");   // (possibly empty) keeps count uniform

        const float* cc = (const float*)(sm + SCC_B + (ch % 3) * 8704);
        const int c0 = ch * 32;

        float acc[2][4][4];
#pragma unroll
        for (int rt = 0; rt < 2; rt++)
#pragma unroll
            for (int nt = 0; nt < 4; nt++) {
                acc[rt][nt][0] = 0.f; acc[rt][nt][1] = 0.f;
                acc[rt][nt][2] = 0.f; acc[rt][nt][3] = 0.f;
            }

        // ks outer, (nt, rt) inner -> 8 independent HMMA chains
#pragma unroll
        for (int ks = 0; ks < 8; ks++) {
            unsigned bs[4][2];
#pragma unroll
            for (int nt = 0; nt < 4; nt++) {
                const float* bp = cc + (nt * 8 + gid) * ROWP + ks * 8 + tig;
                bs[nt][0] = __float_as_uint(bp[0]);
                bs[nt][1] = __float_as_uint(bp[4]);
            }
#pragma unroll
            for (int nt = 0; nt < 4; nt++)
#pragma unroll
                for (int rt = 0; rt < 2; rt++)
                    mma_tf32(acc[rt][nt][0], acc[rt][nt][1], acc[rt][nt][2], acc[rt][nt][3],
                             Af[rt][ks][0], Af[rt][ks][1], Af[rt][ks][2], Af[rt][ks][3],
                             bs[nt][0], bs[nt][1]);
        }

        // epilogue: screen value = fma(-2, dot, c2); top-3 insert
#pragma unroll
        for (int nt = 0; nt < 4; nt++) {
            int   cwA = c0 + nt * 8 + 2 * tig;
            float c2a = sc2[cwA], c2b = sc2[cwA + 1];
#pragma unroll
            for (int rt = 0; rt < 2; rt++) {
#pragma unroll
                for (int h = 0; h < 2; h++) {
                    int s = rt * 2 + h;
                    float dA = __fmaf_rn(-2.f, acc[rt][nt][2 * h],     c2a);
                    float dB = __fmaf_rn(-2.f, acc[rt][nt][2 * h + 1], c2b);
                    if (dA < td[s][2]) {
                        if (dA < td[s][0])      { td[s][2]=td[s][1]; ti[s][2]=ti[s][1]; td[s][1]=td[s][0]; ti[s][1]=ti[s][0]; td[s][0]=dA; ti[s][0]=cwA; }
                        else if (dA < td[s][1]) { td[s][2]=td[s][1]; ti[s][2]=ti[s][1]; td[s][1]=dA; ti[s][1]=cwA; }
                        else                    { td[s][2]=dA; ti[s][2]=cwA; }
                    }
                    if (dB < td[s][2]) {
                        if (dB < td[s][0])      { td[s][2]=td[s][1]; ti[s][2]=ti[s][1]; td[s][1]=td[s][0]; ti[s][1]=ti[s][0]; td[s][0]=dB; ti[s][0]=cwA+1; }
                        else if (dB < td[s][1]) { td[s][2]=td[s][1]; ti[s][2]=ti[s][1]; td[s][1]=dB; ti[s][1]=cwA+1; }
                        else                    { td[s][2]=dB; ti[s][2]=cwA+1; }
                    }
                }
            }
        }
    }

    __syncthreads();   // all warps done with chunk region before aliasing

    // ---- write candidates (12 per token) into aliased buffers ----
#pragma unroll
    for (int s = 0; s < 4; s++) {
        int tok = wbase + (s >> 1) * 16 + gid + 8 * (s & 1);
#pragma unroll
        for (int j = 0; j < 3; j++) {
            cd[tok * 12 + tig * 3 + j] = td[s][j];
            ci[tok * 12 + tig * 3 + j] = ti[s][j];
        }
    }
    __syncthreads();

    // ---- per-token winner: merge 12 + band-gated exact rescore (R8 scheme) ----
    {
        const int tok = tid;
        float d0 = 3.4e38f, d1 = 3.4e38f;
        int   k0 = 0x7fffffff;
#pragma unroll
        for (int i = 0; i < 12; i++) {
            float d = cd[tok * 12 + i];
            int  kk = ci[tok * 12 + i];
            if (d < d0 || (d == d0 && kk < k0)) { d1 = d0; d0 = d; k0 = kk; }
            else if (d < d1) d1 = d;
        }
        int win = k0;
        if (__fsub_rn(d1, d0) < BAND) {
            float xloc[SUBD];
#pragma unroll
            for (int j = 0; j < 16; j++) {
                float4 v = *(const float4*)&sxf[tok * ROWP + 4 * j];
                xloc[4*j] = v.x; xloc[4*j+1] = v.y; xloc[4*j+2] = v.z; xloc[4*j+3] = v.w;
            }
            float x2e = sx2[tok];
            float bde = 3.4e38f; int bke = 0x7fffffff;
            float cut = __fadd_rn(d0, BAND);
#pragma unroll 1
            for (int i = 0; i < 12; i++) {
                if (cd[tok * 12 + i] <= cut) {
                    int kk = ci[tok * 12 + i];
                    const float4* cr = (const float4*)(cbm + (size_t)kk * SUBD);
                    float dot = 0.f;
#pragma unroll
                    for (int i2 = 0; i2 < 16; i2++) {
                        float4 c = cr[i2];
                        dot = __fmaf_rn(xloc[4*i2],     c.x, dot);
                        dot = __fmaf_rn(xloc[4*i2 + 1], c.y, dot);
                        dot = __fmaf_rn(xloc[4*i2 + 2], c.z, dot);
                        dot = __fmaf_rn(xloc[4*i2 + 3], c.w, dot);
                    }
                    float dist = __fadd_rn(__fsub_rn(x2e, __fmul_rn(2.0f, dot)), sc2[kk]);
                    if (dist < bde || (dist == bde && kk < bke)) { bde = dist; bke = kk; }
                }
            }
            win = bke;
        }
        const float4* wv = (const float4*)(cbm + (size_t)win * SUBD);
        float4* qo = (float4*)(out + (size_t)(tokBase + tok) * EMBD + m * SUBD);
#pragma unroll
        for (int i = 0; i < 16; i++) qo[i] = wv[i];
        out[QELEMS + (size_t)(tokBase + tok) * NUM_SUB + m] = (float)win;
    }
}

extern "C" void kernel_launch(void* const* d_in, const int* in_sizes, int n_in,
                              void* d_out, int out_size)
{
    const float* emb = (const float*)d_in[0];  // [8,2048,1024] f32
    const float* cb  = (const float*)d_in[1];  // [16,1024,64]  f32

    c2_kernel<<<NUM_SUB, 1024>>>(cb);

    cudaFuncSetAttribute(pq_main,
                         cudaFuncAttributeMaxDynamicSharedMemorySize, SMEM_BYTES);
    dim3 grid(NTOK / TPB, NUM_SUB);            // (128, 16)
    pq_main<<<grid, TPB, SMEM_BYTES>>>(emb, cb, (float*)d_out);
}